// round 2
// baseline (speedup 1.0000x reference)
#include <cuda_runtime.h>
#include <math.h>

// ---------------------------------------------------------------------------
// GIN_37048387895934 — CSR-gather formulation.
// N=524288 nodes, E=8388608 edges, DIM=32, 8192 graphs x 64 nodes.
// Per launch: build CSR by dst (hist+scan+place), z = x@W1a, then 3 fused
// gather+MLP+stats kernels with BN folded into next layer's weights.
// ---------------------------------------------------------------------------

#define NFEAT 16
#define HDIM 32
#define NPG 64
#define BN_EPS 1e-5f

static constexpr int MAX_NODES = 8192 * 64;       // 524288
static constexpr int MAX_EDGES = MAX_NODES * 16;  // 8388608

// Scratch (__device__ globals; allocation-free rule)
__device__ __align__(256) float g_bufZ[(size_t)MAX_NODES * HDIM];
__device__ __align__(256) float g_bufA[(size_t)MAX_NODES * HDIM];
__device__ __align__(256) float g_bufB[(size_t)MAX_NODES * HDIM];
__device__ int g_rowptr[MAX_NODES + 1];
__device__ int g_cursor[MAX_NODES];
__device__ int g_col[MAX_EDGES];
__device__ int g_bsums[1024];
__device__ float g_stats[3 * 2 * HDIM];   // per-layer [sum(32), sumsq(32)]
__device__ float g_Wmod[HDIM * HDIM];     // diag(sc) @ Wa_next
__device__ float g_cvec[HDIM];            // sh @ Wa_next
__device__ float g_scsh[2 * HDIM];        // sc, sh of most recent BN

// ---------------------------------------------------------------------------
// CSR construction
// ---------------------------------------------------------------------------
__global__ void hist_kernel(const int* __restrict__ dst, int* __restrict__ cnt,
                            int n_edges) {
    int e = blockIdx.x * blockDim.x + threadIdx.x;
    if (e < n_edges) atomicAdd(&cnt[dst[e]], 1);
}

// Per-block inclusive scan of 1024 counts -> rowptr1 (= rowptr+1), block sums.
__global__ void scan1_kernel(const int* __restrict__ cnt, int* __restrict__ rowptr1,
                             int* __restrict__ bsums, int n) {
    __shared__ int sh[1024];
    int i = blockIdx.x * 1024 + threadIdx.x;
    int v = (i < n) ? cnt[i] : 0;
    sh[threadIdx.x] = v;
    __syncthreads();
#pragma unroll
    for (int off = 1; off < 1024; off <<= 1) {
        int t = 0;
        if (threadIdx.x >= off) t = sh[threadIdx.x - off];
        __syncthreads();
        if (threadIdx.x >= off) sh[threadIdx.x] += t;
        __syncthreads();
    }
    if (i < n) rowptr1[i] = sh[threadIdx.x];
    if (threadIdx.x == 1023) bsums[blockIdx.x] = sh[1023];
}

// Exclusive scan of block sums (single block, up to 1024 blocks).
__global__ void scan2_kernel(int* __restrict__ bsums, int nb) {
    __shared__ int sh[1024];
    int v = (threadIdx.x < nb) ? bsums[threadIdx.x] : 0;
    sh[threadIdx.x] = v;
    __syncthreads();
#pragma unroll
    for (int off = 1; off < 1024; off <<= 1) {
        int t = 0;
        if (threadIdx.x >= off) t = sh[threadIdx.x - off];
        __syncthreads();
        if (threadIdx.x >= off) sh[threadIdx.x] += t;
        __syncthreads();
    }
    if (threadIdx.x < nb) bsums[threadIdx.x] = sh[threadIdx.x] - v;  // exclusive
}

__global__ void scan3_kernel(int* __restrict__ rowptr, const int* __restrict__ bsums,
                             int n) {
    int i = blockIdx.x * blockDim.x + threadIdx.x;
    if (i < n) rowptr[i + 1] += bsums[i >> 10];
    if (i == 0) rowptr[0] = 0;
}

__global__ void place_kernel(const int* __restrict__ src, const int* __restrict__ dst,
                             int* __restrict__ cursor, int* __restrict__ col,
                             int n_edges) {
    int e = blockIdx.x * blockDim.x + threadIdx.x;
    if (e < n_edges) {
        int p = atomicAdd(&cursor[dst[e]], 1);
        col[p] = src[e];
    }
}

// ---------------------------------------------------------------------------
// z = x @ W1a  (16 -> 32), warp-per-node, grid-stride, coalesced I/O
// ---------------------------------------------------------------------------
__global__ void zprep_kernel(const float* __restrict__ x, const float* __restrict__ W,
                             float* __restrict__ z, int n_nodes) {
    __shared__ float sW[NFEAT * HDIM];
    for (int i = threadIdx.x; i < NFEAT * HDIM; i += blockDim.x) sW[i] = W[i];
    __syncthreads();
    int lane = threadIdx.x & 31;
    int gw = (blockIdx.x * blockDim.x + threadIdx.x) >> 5;
    int nwarps = (gridDim.x * blockDim.x) >> 5;
    for (int node = gw; node < n_nodes; node += nwarps) {
        float xv = (lane < NFEAT) ? x[(size_t)node * NFEAT + lane] : 0.0f;
        float u = 0.0f;
#pragma unroll
        for (int i = 0; i < NFEAT; i++) {
            float xi = __shfl_sync(0xFFFFFFFFu, xv, i);
            u = fmaf(xi, sW[i * HDIM + lane], u);
        }
        z[(size_t)node * HDIM + lane] = u;
    }
}

// ---------------------------------------------------------------------------
// Fused layer: coalesced CSR gather (warp-per-node, lane=channel) -> shared
// tile -> thread-per-node MLP -> BN stats. BN of previous layer folded into
// Wmod/cvec when PRE=true. Block handles exactly 256 nodes.
// ---------------------------------------------------------------------------
template <bool PRE>
__global__ __launch_bounds__(256) void layer_kernel(
    const float* __restrict__ vin, const int* __restrict__ rowptr,
    const int* __restrict__ col, const float* __restrict__ Wmod,
    const float* __restrict__ cvec, const float* __restrict__ ba,
    const float* __restrict__ Wb, const float* __restrict__ bb,
    float* __restrict__ vout, float* __restrict__ stats, int n_nodes) {
    __shared__ float tile[256 * 33];
    __shared__ float sWa[HDIM * HDIM];
    __shared__ float sWb[HDIM * HDIM];
    __shared__ float sba[HDIM], sbb[HDIM], scv[HDIM];
    __shared__ float ps[8 * 32], pq[8 * 32];

    if (PRE)
        for (int i = threadIdx.x; i < HDIM * HDIM; i += 256) sWa[i] = Wmod[i];
    for (int i = threadIdx.x; i < HDIM * HDIM; i += 256) sWb[i] = Wb[i];
    if (threadIdx.x < HDIM) {
        sba[threadIdx.x] = ba[threadIdx.x];
        sbb[threadIdx.x] = bb[threadIdx.x];
        scv[threadIdx.x] = PRE ? cvec[threadIdx.x] : 0.0f;
    }
    __syncthreads();

    int warp = threadIdx.x >> 5;
    int lane = threadIdx.x & 31;
    int base = blockIdx.x * 256;

    // ---- Gather phase: warp w gathers nodes [base+32w, base+32w+32) ----
    for (int k = 0; k < 32; k++) {
        int row = warp * 32 + k;
        int node = base + row;
        float s0 = 0.0f, s1 = 0.0f, s2 = 0.0f, s3 = 0.0f;
        float degf = 0.0f;
        if (node < n_nodes) {
            int r0 = __ldg(&rowptr[node]);
            int r1 = __ldg(&rowptr[node + 1]);
            degf = (float)(r1 - r0);
            s0 = vin[(size_t)node * HDIM + lane];  // self
            int e = r0;
            while (e < r1) {
                int m = r1 - e;
                if (m > 32) m = 32;
                int cidx = (lane < m) ? col[e + lane] : 0;
                int i = 0;
                for (; i + 4 <= m; i += 4) {
                    int nb0 = __shfl_sync(0xFFFFFFFFu, cidx, i);
                    int nb1 = __shfl_sync(0xFFFFFFFFu, cidx, i + 1);
                    int nb2 = __shfl_sync(0xFFFFFFFFu, cidx, i + 2);
                    int nb3 = __shfl_sync(0xFFFFFFFFu, cidx, i + 3);
                    s0 += vin[(size_t)nb0 * HDIM + lane];
                    s1 += vin[(size_t)nb1 * HDIM + lane];
                    s2 += vin[(size_t)nb2 * HDIM + lane];
                    s3 += vin[(size_t)nb3 * HDIM + lane];
                }
                for (; i < m; i++) {
                    int nb = __shfl_sync(0xFFFFFFFFu, cidx, i);
                    s0 += vin[(size_t)nb * HDIM + lane];
                }
                e += m;
            }
        }
        tile[row * 33 + lane] = (s0 + s1) + (s2 + s3);
        if (lane == 0) tile[row * 33 + 32] = degf;
    }
    __syncthreads();

    // ---- MLP phase: thread tid handles node base+tid (tile row tid) ----
    int tid = threadIdx.x;
    bool valid = (base + tid) < n_nodes;
    float degp1 = tile[tid * 33 + 32] + 1.0f;
    float u[HDIM];
    if (PRE) {
#pragma unroll
        for (int j = 0; j < HDIM; j++) u[j] = sba[j] + degp1 * scv[j];
#pragma unroll
        for (int i = 0; i < HDIM; i++) {
            float ti = tile[tid * 33 + i];
#pragma unroll
            for (int j = 0; j < HDIM; j++) u[j] = fmaf(ti, sWa[i * HDIM + j], u[j]);
        }
    } else {
#pragma unroll
        for (int j = 0; j < HDIM; j++) u[j] = tile[tid * 33 + j] + sba[j];
    }
    // relu, stash u in own tile row (cuts register peak for second matmul)
#pragma unroll
    for (int j = 0; j < HDIM; j++) tile[tid * 33 + j] = fmaxf(u[j], 0.0f);

    float v[HDIM];
#pragma unroll
    for (int j = 0; j < HDIM; j++) v[j] = sbb[j];
#pragma unroll
    for (int i = 0; i < HDIM; i++) {
        float ui = tile[tid * 33 + i];
#pragma unroll
        for (int j = 0; j < HDIM; j++) v[j] = fmaf(ui, sWb[i * HDIM + j], v[j]);
    }
#pragma unroll
    for (int j = 0; j < HDIM; j++)
        tile[tid * 33 + j] = valid ? fmaxf(v[j], 0.0f) : 0.0f;
    __syncthreads();

    // ---- Coalesced store + BN stats column reduction ----
    for (int k = 0; k < 32; k++) {
        int row = warp * 32 + k;
        int node = base + row;
        if (node < n_nodes)
            vout[(size_t)node * HDIM + lane] = tile[row * 33 + lane];
    }
    float s = 0.0f, q = 0.0f;
#pragma unroll
    for (int k = 0; k < 32; k++) {
        float vv = tile[(warp * 32 + k) * 33 + lane];
        s += vv;
        q += vv * vv;
    }
    ps[warp * 32 + lane] = s;
    pq[warp * 32 + lane] = q;
    __syncthreads();
    if (tid < 32) {
        float ss = 0.0f, qq = 0.0f;
#pragma unroll
        for (int k = 0; k < 8; k++) {
            ss += ps[k * 32 + tid];
            qq += pq[k * 32 + tid];
        }
        atomicAdd(&stats[tid], ss);
        atomicAdd(&stats[32 + tid], qq);
    }
}

// ---------------------------------------------------------------------------
// Prep: stats -> (sc, sh); optionally fold into next layer: Wmod = diag(sc)@Wa,
// cvec = sh @ Wa. Wa==nullptr => only write scsh (for pooling).
// ---------------------------------------------------------------------------
__global__ void prep_kernel(const float* __restrict__ stats,
                            const float* __restrict__ gamma,
                            const float* __restrict__ beta,
                            const float* __restrict__ Wa, float* __restrict__ Wmod,
                            float* __restrict__ cvec, float* __restrict__ scsh,
                            float invN) {
    __shared__ float ssc[HDIM], ssh[HDIM];
    int tid = threadIdx.x;
    if (tid < HDIM) {
        float m = stats[tid] * invN;
        float var = stats[HDIM + tid] * invN - m * m;
        float sc = gamma[tid] * rsqrtf(var + BN_EPS);
        float sh = beta[tid] - m * sc;
        ssc[tid] = sc;
        ssh[tid] = sh;
        scsh[tid] = sc;
        scsh[HDIM + tid] = sh;
    }
    __syncthreads();
    if (Wa != nullptr) {
        if (tid < HDIM * HDIM) Wmod[tid] = ssc[tid >> 5] * Wa[tid];
        if (tid < HDIM) {
            float c = 0.0f;
#pragma unroll
            for (int i = 0; i < HDIM; i++) c += ssh[i] * Wa[i * HDIM + tid];
            cvec[tid] = c;
        }
    }
}

// ---------------------------------------------------------------------------
// Pool (sum 64 nodes) with final BN affine applied analytically, then 32->2
// linear + log_softmax. Warp per graph, lane = channel.
// ---------------------------------------------------------------------------
__global__ void pool_kernel(const float* __restrict__ v, const float* __restrict__ scsh,
                            const float* __restrict__ Wf, const float* __restrict__ bf,
                            float* __restrict__ out, int n_graphs) {
    int g = (blockIdx.x * blockDim.x + threadIdx.x) >> 5;
    int lane = threadIdx.x & 31;
    if (g >= n_graphs) return;
    const float* base = v + (size_t)g * NPG * HDIM;
    float s = 0.0f;
#pragma unroll 8
    for (int n = 0; n < NPG; n++) s += base[n * HDIM + lane];
    s = scsh[lane] * s + (float)NPG * scsh[HDIM + lane];
    float p0 = s * Wf[lane * 2 + 0];
    float p1 = s * Wf[lane * 2 + 1];
#pragma unroll
    for (int off = 16; off > 0; off >>= 1) {
        p0 += __shfl_xor_sync(0xFFFFFFFFu, p0, off);
        p1 += __shfl_xor_sync(0xFFFFFFFFu, p1, off);
    }
    if (lane == 0) {
        float l0 = p0 + bf[0];
        float l1 = p1 + bf[1];
        float m = fmaxf(l0, l1);
        float lse = m + logf(expf(l0 - m) + expf(l1 - m));
        out[g * 2 + 0] = l0 - lse;
        out[g * 2 + 1] = l1 - lse;
    }
}

// ---------------------------------------------------------------------------
// Launch
// ---------------------------------------------------------------------------
extern "C" void kernel_launch(void* const* d_in, const int* in_sizes, int n_in,
                              void* d_out, int out_size) {
    const float* x   = (const float*)d_in[0];
    const int*   ei  = (const int*)d_in[1];
    const float* W1a = (const float*)d_in[3];
    const float* b1a = (const float*)d_in[4];
    const float* W1b = (const float*)d_in[5];
    const float* b1b = (const float*)d_in[6];
    const float* W2a = (const float*)d_in[7];
    const float* b2a = (const float*)d_in[8];
    const float* W2b = (const float*)d_in[9];
    const float* b2b = (const float*)d_in[10];
    const float* W3a = (const float*)d_in[11];
    const float* b3a = (const float*)d_in[12];
    const float* W3b = (const float*)d_in[13];
    const float* b3b = (const float*)d_in[14];
    const float* g1  = (const float*)d_in[15];
    const float* be1 = (const float*)d_in[16];
    const float* g2  = (const float*)d_in[17];
    const float* be2 = (const float*)d_in[18];
    const float* g3  = (const float*)d_in[19];
    const float* be3 = (const float*)d_in[20];
    const float* Wf  = (const float*)d_in[21];
    const float* bf  = (const float*)d_in[22];
    float* out = (float*)d_out;

    int n_nodes  = in_sizes[0] / NFEAT;
    int n_edges  = in_sizes[1] / 2;
    int n_graphs = n_nodes / NPG;
    const int* src = ei;
    const int* dst = ei + n_edges;

    float *bufZ, *bufA, *bufB, *stats, *Wmod, *cvec, *scsh;
    int *rowptr, *cursor, *colA, *bsums;
    cudaGetSymbolAddress((void**)&bufZ, g_bufZ);
    cudaGetSymbolAddress((void**)&bufA, g_bufA);
    cudaGetSymbolAddress((void**)&bufB, g_bufB);
    cudaGetSymbolAddress((void**)&stats, g_stats);
    cudaGetSymbolAddress((void**)&Wmod, g_Wmod);
    cudaGetSymbolAddress((void**)&cvec, g_cvec);
    cudaGetSymbolAddress((void**)&scsh, g_scsh);
    cudaGetSymbolAddress((void**)&rowptr, g_rowptr);
    cudaGetSymbolAddress((void**)&cursor, g_cursor);
    cudaGetSymbolAddress((void**)&colA, g_col);
    cudaGetSymbolAddress((void**)&bsums, g_bsums);

    float invN = 1.0f / (float)n_nodes;
    int grid_e = (n_edges + 255) / 256;
    int grid_n = (n_nodes + 255) / 256;
    int nb = (n_nodes + 1023) / 1024;

    // ---- CSR build (by dst) ----
    cudaMemsetAsync(cursor, 0, (size_t)n_nodes * sizeof(int), 0);
    hist_kernel<<<grid_e, 256>>>(dst, cursor, n_edges);
    scan1_kernel<<<nb, 1024>>>(cursor, rowptr + 1, bsums, n_nodes);
    scan2_kernel<<<1, 1024>>>(bsums, nb);
    scan3_kernel<<<grid_n, 256>>>(rowptr, bsums, n_nodes);
    cudaMemcpyAsync(cursor, rowptr, (size_t)n_nodes * sizeof(int),
                    cudaMemcpyDeviceToDevice, 0);
    place_kernel<<<grid_e, 256>>>(src, dst, cursor, colA, n_edges);

    cudaMemsetAsync(stats, 0, 6 * HDIM * sizeof(float), 0);

    // ---- z = x @ W1a ----
    zprep_kernel<<<2048, 256>>>(x, W1a, bufZ, n_nodes);

    // ---- Layer 1: u = relu(z_i + sum_j z_j + b1a); v = relu(u@W1b + b1b) ----
    layer_kernel<false><<<grid_n, 256>>>(bufZ, rowptr, colA, nullptr, nullptr, b1a,
                                         W1b, b1b, bufA, stats + 0, n_nodes);
    prep_kernel<<<1, 1024>>>(stats + 0, g1, be1, W2a, Wmod, cvec, scsh, invN);

    // ---- Layer 2 (BN1 folded into Wmod/cvec) ----
    layer_kernel<true><<<grid_n, 256>>>(bufA, rowptr, colA, Wmod, cvec, b2a,
                                        W2b, b2b, bufB, stats + 64, n_nodes);
    prep_kernel<<<1, 1024>>>(stats + 64, g2, be2, W3a, Wmod, cvec, scsh, invN);

    // ---- Layer 3 (BN2 folded) ----
    layer_kernel<true><<<grid_n, 256>>>(bufB, rowptr, colA, Wmod, cvec, b3a,
                                        W3b, b3b, bufA, stats + 128, n_nodes);
    prep_kernel<<<1, 1024>>>(stats + 128, g3, be3, nullptr, Wmod, cvec, scsh, invN);

    // ---- Pool + head (BN3 affine applied on pooled sums) ----
    int grid_p = (n_graphs * 32 + 255) / 256;
    pool_kernel<<<grid_p, 256>>>(bufA, scsh, Wf, bf, out, n_graphs);
}

// round 3
// speedup vs baseline: 1.8221x; 1.8221x over previous
#include <cuda_runtime.h>
#include <math.h>

// ---------------------------------------------------------------------------
// GIN_37048387895934 — CSR gather (warp-per-node) + thread-per-node MLP.
// N=524288 nodes, E=8388608 edges, DIM=32, 8192 graphs x 64 nodes.
// ---------------------------------------------------------------------------

#define NFEAT 16
#define HDIM 32
#define NPG 64
#define BN_EPS 1e-5f

static constexpr int MAX_NODES = 8192 * 64;       // 524288
static constexpr int MAX_EDGES = MAX_NODES * 16;  // 8388608

__device__ __align__(256) float g_bufZ[(size_t)MAX_NODES * HDIM];
__device__ __align__(256) float g_bufA[(size_t)MAX_NODES * HDIM];
__device__ __align__(256) float g_bufB[(size_t)MAX_NODES * HDIM];
__device__ __align__(256) float g_agg [(size_t)MAX_NODES * HDIM];
__device__ int g_rowptr[MAX_NODES + 1];
__device__ int g_cursor[MAX_NODES];
__device__ int g_col[MAX_EDGES];
__device__ int g_bsums[1024];
__device__ float g_stats[3 * 2 * HDIM];
__device__ float g_Wmod[HDIM * HDIM];
__device__ float g_cvec[HDIM];
__device__ float g_scsh[2 * HDIM];

// ---------------------------------------------------------------------------
// CSR construction
// ---------------------------------------------------------------------------
__global__ void hist_kernel(const int* __restrict__ dst, int* __restrict__ cnt,
                            int n_edges) {
    int e = blockIdx.x * blockDim.x + threadIdx.x;
    if (e < n_edges) atomicAdd(&cnt[dst[e]], 1);
}

__global__ void scan1_kernel(const int* __restrict__ cnt, int* __restrict__ rowptr1,
                             int* __restrict__ bsums, int n) {
    __shared__ int sh[1024];
    int i = blockIdx.x * 1024 + threadIdx.x;
    int v = (i < n) ? cnt[i] : 0;
    sh[threadIdx.x] = v;
    __syncthreads();
#pragma unroll
    for (int off = 1; off < 1024; off <<= 1) {
        int t = 0;
        if (threadIdx.x >= off) t = sh[threadIdx.x - off];
        __syncthreads();
        if (threadIdx.x >= off) sh[threadIdx.x] += t;
        __syncthreads();
    }
    if (i < n) rowptr1[i] = sh[threadIdx.x];
    if (threadIdx.x == 1023) bsums[blockIdx.x] = sh[1023];
}

__global__ void scan2_kernel(int* __restrict__ bsums, int nb) {
    __shared__ int sh[1024];
    int v = (threadIdx.x < nb) ? bsums[threadIdx.x] : 0;
    sh[threadIdx.x] = v;
    __syncthreads();
#pragma unroll
    for (int off = 1; off < 1024; off <<= 1) {
        int t = 0;
        if (threadIdx.x >= off) t = sh[threadIdx.x - off];
        __syncthreads();
        if (threadIdx.x >= off) sh[threadIdx.x] += t;
        __syncthreads();
    }
    if (threadIdx.x < nb) bsums[threadIdx.x] = sh[threadIdx.x] - v;  // exclusive
}

// Finalize rowptr and also write cursor (replaces the D2D memcpy).
__global__ void scan3_kernel(int* __restrict__ rowptr, int* __restrict__ cursor,
                             const int* __restrict__ bsums, int n) {
    int i = blockIdx.x * blockDim.x + threadIdx.x;
    if (i < n) {
        int v = rowptr[i + 1] + bsums[i >> 10];
        rowptr[i + 1] = v;
        if (i + 1 < n) cursor[i + 1] = v;
    }
    if (i == 0) {
        rowptr[0] = 0;
        cursor[0] = 0;
    }
}

__global__ void place_kernel(const int* __restrict__ src, const int* __restrict__ dst,
                             int* __restrict__ cursor, int* __restrict__ col,
                             int n_edges) {
    int e = blockIdx.x * blockDim.x + threadIdx.x;
    if (e < n_edges) {
        int p = atomicAdd(&cursor[dst[e]], 1);
        col[p] = src[e];
    }
}

// ---------------------------------------------------------------------------
// z = x @ W1a  (16 -> 32)
// ---------------------------------------------------------------------------
__global__ void zprep_kernel(const float* __restrict__ x, const float* __restrict__ W,
                             float* __restrict__ z, int n_nodes) {
    __shared__ float sW[NFEAT * HDIM];
    for (int i = threadIdx.x; i < NFEAT * HDIM; i += blockDim.x) sW[i] = W[i];
    __syncthreads();
    int lane = threadIdx.x & 31;
    int gw = (blockIdx.x * blockDim.x + threadIdx.x) >> 5;
    int nwarps = (gridDim.x * blockDim.x) >> 5;
    for (int node = gw; node < n_nodes; node += nwarps) {
        float xv = (lane < NFEAT) ? x[(size_t)node * NFEAT + lane] : 0.0f;
        float u = 0.0f;
#pragma unroll
        for (int i = 0; i < NFEAT; i++) {
            float xi = __shfl_sync(0xFFFFFFFFu, xv, i);
            u = fmaf(xi, sW[i * HDIM + lane], u);
        }
        z[(size_t)node * HDIM + lane] = u;
    }
}

// ---------------------------------------------------------------------------
// Gather: one warp per node, lane = channel. agg[node] = vin[node] + sum_nb.
// 8 accumulators -> 8 independent 128B loads in flight per warp.
// ---------------------------------------------------------------------------
__global__ __launch_bounds__(256) void gather_kernel(
    const float* __restrict__ vin, const int* __restrict__ rowptr,
    const int* __restrict__ col, float* __restrict__ agg, int n_nodes) {
    int lane = threadIdx.x & 31;
    int node = (blockIdx.x * blockDim.x + threadIdx.x) >> 5;
    if (node >= n_nodes) return;
    int r0 = __ldg(&rowptr[node]);
    int r1 = __ldg(&rowptr[node + 1]);
    float s0 = vin[(size_t)node * HDIM + lane];
    float s1 = 0.f, s2 = 0.f, s3 = 0.f, s4 = 0.f, s5 = 0.f, s6 = 0.f, s7 = 0.f;
    int e = r0;
    while (e < r1) {
        int m = r1 - e;
        if (m > 32) m = 32;
        int cidx = (lane < m) ? col[e + lane] : 0;
        int i = 0;
        for (; i + 8 <= m; i += 8) {
            int n0 = __shfl_sync(0xFFFFFFFFu, cidx, i);
            int n1 = __shfl_sync(0xFFFFFFFFu, cidx, i + 1);
            int n2 = __shfl_sync(0xFFFFFFFFu, cidx, i + 2);
            int n3 = __shfl_sync(0xFFFFFFFFu, cidx, i + 3);
            int n4 = __shfl_sync(0xFFFFFFFFu, cidx, i + 4);
            int n5 = __shfl_sync(0xFFFFFFFFu, cidx, i + 5);
            int n6 = __shfl_sync(0xFFFFFFFFu, cidx, i + 6);
            int n7 = __shfl_sync(0xFFFFFFFFu, cidx, i + 7);
            s0 += vin[(size_t)n0 * HDIM + lane];
            s1 += vin[(size_t)n1 * HDIM + lane];
            s2 += vin[(size_t)n2 * HDIM + lane];
            s3 += vin[(size_t)n3 * HDIM + lane];
            s4 += vin[(size_t)n4 * HDIM + lane];
            s5 += vin[(size_t)n5 * HDIM + lane];
            s6 += vin[(size_t)n6 * HDIM + lane];
            s7 += vin[(size_t)n7 * HDIM + lane];
        }
        for (; i < m; i++) {
            int nb = __shfl_sync(0xFFFFFFFFu, cidx, i);
            s1 += vin[(size_t)nb * HDIM + lane];
        }
        e += m;
    }
    agg[(size_t)node * HDIM + lane] = ((s0 + s1) + (s2 + s3)) + ((s4 + s5) + (s6 + s7));
}

// ---------------------------------------------------------------------------
// MLP: thread-per-node. t = agg row (self included). PRE: fold prev BN via
// Wmod=diag(sc)@Wa, cvec=sh@Wa (needs deg+1 from rowptr). Stats fused.
// ---------------------------------------------------------------------------
template <bool PRE>
__global__ __launch_bounds__(256) void mlp_kernel(
    const float* __restrict__ agg, const int* __restrict__ rowptr,
    const float* __restrict__ Wmod, const float* __restrict__ cvec,
    const float* __restrict__ ba, const float* __restrict__ Wb,
    const float* __restrict__ bb, float* __restrict__ vout,
    float* __restrict__ stats, int n_nodes) {
    __shared__ float tile[256 * 33];
    __shared__ float sWa[HDIM * HDIM];
    __shared__ float sWb[HDIM * HDIM];
    __shared__ float sba[HDIM], sbb[HDIM], scv[HDIM];
    __shared__ float ps[8 * 32], pq[8 * 32];

    if (PRE)
        for (int i = threadIdx.x; i < HDIM * HDIM; i += 256) sWa[i] = Wmod[i];
    for (int i = threadIdx.x; i < HDIM * HDIM; i += 256) sWb[i] = Wb[i];
    if (threadIdx.x < HDIM) {
        sba[threadIdx.x] = ba[threadIdx.x];
        sbb[threadIdx.x] = bb[threadIdx.x];
        scv[threadIdx.x] = PRE ? cvec[threadIdx.x] : 0.0f;
    }
    __syncthreads();

    int warp = threadIdx.x >> 5;
    int lane = threadIdx.x & 31;
    int base = blockIdx.x * 256;
    int tid = threadIdx.x;

    // Coalesced load of 32 node rows per warp into tile.
    for (int k = 0; k < 32; k++) {
        int row = warp * 32 + k;
        int node = base + row;
        tile[row * 33 + lane] =
            (node < n_nodes) ? agg[(size_t)node * HDIM + lane] : 0.0f;
    }
    __syncthreads();

    bool valid = (base + tid) < n_nodes;
    float u[HDIM];
    if (PRE) {
        float degp1 = 1.0f;
        if (valid) degp1 = (float)(rowptr[base + tid + 1] - rowptr[base + tid]) + 1.0f;
#pragma unroll
        for (int j = 0; j < HDIM; j++) u[j] = sba[j] + degp1 * scv[j];
#pragma unroll
        for (int i = 0; i < HDIM; i++) {
            float ti = tile[tid * 33 + i];
#pragma unroll
            for (int j = 0; j < HDIM; j++) u[j] = fmaf(ti, sWa[i * HDIM + j], u[j]);
        }
    } else {
#pragma unroll
        for (int j = 0; j < HDIM; j++) u[j] = tile[tid * 33 + j] + sba[j];
    }
#pragma unroll
    for (int j = 0; j < HDIM; j++) tile[tid * 33 + j] = fmaxf(u[j], 0.0f);

    float v[HDIM];
#pragma unroll
    for (int j = 0; j < HDIM; j++) v[j] = sbb[j];
#pragma unroll
    for (int i = 0; i < HDIM; i++) {
        float ui = tile[tid * 33 + i];
#pragma unroll
        for (int j = 0; j < HDIM; j++) v[j] = fmaf(ui, sWb[i * HDIM + j], v[j]);
    }
#pragma unroll
    for (int j = 0; j < HDIM; j++)
        tile[tid * 33 + j] = valid ? fmaxf(v[j], 0.0f) : 0.0f;
    __syncthreads();

    // Coalesced store + column reduction for BN stats.
    for (int k = 0; k < 32; k++) {
        int row = warp * 32 + k;
        int node = base + row;
        if (node < n_nodes)
            vout[(size_t)node * HDIM + lane] = tile[row * 33 + lane];
    }
    float s = 0.0f, q = 0.0f;
#pragma unroll
    for (int k = 0; k < 32; k++) {
        float vv = tile[(warp * 32 + k) * 33 + lane];
        s += vv;
        q += vv * vv;
    }
    ps[warp * 32 + lane] = s;
    pq[warp * 32 + lane] = q;
    __syncthreads();
    if (tid < 32) {
        float ss = 0.0f, qq = 0.0f;
#pragma unroll
        for (int k = 0; k < 8; k++) {
            ss += ps[k * 32 + tid];
            qq += pq[k * 32 + tid];
        }
        atomicAdd(&stats[tid], ss);
        atomicAdd(&stats[32 + tid], qq);
    }
}

// ---------------------------------------------------------------------------
// Prep: stats -> (sc, sh); fold into next Wa if given.
// ---------------------------------------------------------------------------
__global__ void prep_kernel(const float* __restrict__ stats,
                            const float* __restrict__ gamma,
                            const float* __restrict__ beta,
                            const float* __restrict__ Wa, float* __restrict__ Wmod,
                            float* __restrict__ cvec, float* __restrict__ scsh,
                            float invN) {
    __shared__ float ssc[HDIM], ssh[HDIM];
    int tid = threadIdx.x;
    if (tid < HDIM) {
        float m = stats[tid] * invN;
        float var = stats[HDIM + tid] * invN - m * m;
        float sc = gamma[tid] * rsqrtf(var + BN_EPS);
        float sh = beta[tid] - m * sc;
        ssc[tid] = sc;
        ssh[tid] = sh;
        scsh[tid] = sc;
        scsh[HDIM + tid] = sh;
    }
    __syncthreads();
    if (Wa != nullptr) {
        if (tid < HDIM * HDIM) Wmod[tid] = ssc[tid >> 5] * Wa[tid];
        if (tid < HDIM) {
            float c = 0.0f;
#pragma unroll
            for (int i = 0; i < HDIM; i++) c += ssh[i] * Wa[i * HDIM + tid];
            cvec[tid] = c;
        }
    }
}

// ---------------------------------------------------------------------------
// Pool + head with final BN affine applied analytically.
// ---------------------------------------------------------------------------
__global__ void pool_kernel(const float* __restrict__ v, const float* __restrict__ scsh,
                            const float* __restrict__ Wf, const float* __restrict__ bf,
                            float* __restrict__ out, int n_graphs) {
    int g = (blockIdx.x * blockDim.x + threadIdx.x) >> 5;
    int lane = threadIdx.x & 31;
    if (g >= n_graphs) return;
    const float* base = v + (size_t)g * NPG * HDIM;
    float s = 0.0f;
#pragma unroll 8
    for (int n = 0; n < NPG; n++) s += base[n * HDIM + lane];
    s = scsh[lane] * s + (float)NPG * scsh[HDIM + lane];
    float p0 = s * Wf[lane * 2 + 0];
    float p1 = s * Wf[lane * 2 + 1];
#pragma unroll
    for (int off = 16; off > 0; off >>= 1) {
        p0 += __shfl_xor_sync(0xFFFFFFFFu, p0, off);
        p1 += __shfl_xor_sync(0xFFFFFFFFu, p1, off);
    }
    if (lane == 0) {
        float l0 = p0 + bf[0];
        float l1 = p1 + bf[1];
        float m = fmaxf(l0, l1);
        float lse = m + logf(expf(l0 - m) + expf(l1 - m));
        out[g * 2 + 0] = l0 - lse;
        out[g * 2 + 1] = l1 - lse;
    }
}

// ---------------------------------------------------------------------------
// Launch
// ---------------------------------------------------------------------------
extern "C" void kernel_launch(void* const* d_in, const int* in_sizes, int n_in,
                              void* d_out, int out_size) {
    const float* x   = (const float*)d_in[0];
    const int*   ei  = (const int*)d_in[1];
    const float* W1a = (const float*)d_in[3];
    const float* b1a = (const float*)d_in[4];
    const float* W1b = (const float*)d_in[5];
    const float* b1b = (const float*)d_in[6];
    const float* W2a = (const float*)d_in[7];
    const float* b2a = (const float*)d_in[8];
    const float* W2b = (const float*)d_in[9];
    const float* b2b = (const float*)d_in[10];
    const float* W3a = (const float*)d_in[11];
    const float* b3a = (const float*)d_in[12];
    const float* W3b = (const float*)d_in[13];
    const float* b3b = (const float*)d_in[14];
    const float* g1  = (const float*)d_in[15];
    const float* be1 = (const float*)d_in[16];
    const float* g2  = (const float*)d_in[17];
    const float* be2 = (const float*)d_in[18];
    const float* g3  = (const float*)d_in[19];
    const float* be3 = (const float*)d_in[20];
    const float* Wf  = (const float*)d_in[21];
    const float* bf  = (const float*)d_in[22];
    float* out = (float*)d_out;

    int n_nodes  = in_sizes[0] / NFEAT;
    int n_edges  = in_sizes[1] / 2;
    int n_graphs = n_nodes / NPG;
    const int* src = ei;
    const int* dst = ei + n_edges;

    float *bufZ, *bufA, *bufB, *agg, *stats, *Wmod, *cvec, *scsh;
    int *rowptr, *cursor, *colA, *bsums;
    cudaGetSymbolAddress((void**)&bufZ, g_bufZ);
    cudaGetSymbolAddress((void**)&bufA, g_bufA);
    cudaGetSymbolAddress((void**)&bufB, g_bufB);
    cudaGetSymbolAddress((void**)&agg, g_agg);
    cudaGetSymbolAddress((void**)&stats, g_stats);
    cudaGetSymbolAddress((void**)&Wmod, g_Wmod);
    cudaGetSymbolAddress((void**)&cvec, g_cvec);
    cudaGetSymbolAddress((void**)&scsh, g_scsh);
    cudaGetSymbolAddress((void**)&rowptr, g_rowptr);
    cudaGetSymbolAddress((void**)&cursor, g_cursor);
    cudaGetSymbolAddress((void**)&colA, g_col);
    cudaGetSymbolAddress((void**)&bsums, g_bsums);

    float invN = 1.0f / (float)n_nodes;
    int grid_e = (n_edges + 255) / 256;
    int grid_n = (n_nodes + 255) / 256;   // mlp: thread per node
    int grid_g = (n_nodes * 32 + 255) / 256;  // gather: warp per node
    int nb = (n_nodes + 1023) / 1024;

    // ---- CSR build (by dst) ----
    cudaMemsetAsync(cursor, 0, (size_t)n_nodes * sizeof(int), 0);
    cudaMemsetAsync(stats, 0, 6 * HDIM * sizeof(float), 0);
    hist_kernel<<<grid_e, 256>>>(dst, cursor, n_edges);
    scan1_kernel<<<nb, 1024>>>(cursor, rowptr + 1, bsums, n_nodes);
    scan2_kernel<<<1, 1024>>>(bsums, nb);
    scan3_kernel<<<grid_n, 256>>>(rowptr, cursor, bsums, n_nodes);
    place_kernel<<<grid_e, 256>>>(src, dst, cursor, colA, n_edges);

    // ---- z = x @ W1a ----
    zprep_kernel<<<2048, 256>>>(x, W1a, bufZ, n_nodes);

    // ---- Layer 1 ----
    gather_kernel<<<grid_g, 256>>>(bufZ, rowptr, colA, agg, n_nodes);
    mlp_kernel<false><<<grid_n, 256>>>(agg, rowptr, nullptr, nullptr, b1a,
                                       W1b, b1b, bufA, stats + 0, n_nodes);
    prep_kernel<<<1, 1024>>>(stats + 0, g1, be1, W2a, Wmod, cvec, scsh, invN);

    // ---- Layer 2 ----
    gather_kernel<<<grid_g, 256>>>(bufA, rowptr, colA, agg, n_nodes);
    mlp_kernel<true><<<grid_n, 256>>>(agg, rowptr, Wmod, cvec, b2a,
                                      W2b, b2b, bufB, stats + 64, n_nodes);
    prep_kernel<<<1, 1024>>>(stats + 64, g2, be2, W3a, Wmod, cvec, scsh, invN);

    // ---- Layer 3 ----
    gather_kernel<<<grid_g, 256>>>(bufB, rowptr, colA, agg, n_nodes);
    mlp_kernel<true><<<grid_n, 256>>>(agg, rowptr, Wmod, cvec, b3a,
                                      W3b, b3b, bufA, stats + 128, n_nodes);
    prep_kernel<<<1, 1024>>>(stats + 128, g3, be3, nullptr, Wmod, cvec, scsh, invN);

    // ---- Pool + head ----
    int grid_p = (n_graphs * 32 + 255) / 256;
    pool_kernel<<<grid_p, 256>>>(bufA, scsh, Wf, bf, out, n_graphs);
}